// round 1
// baseline (speedup 1.0000x reference)
#include <cuda_runtime.h>
#include <cuda_bf16.h>
#include <math.h>

// Problem constants
#define EMBED 1024
#define NHEADS 16
#define HDIM 64
#define BATCH 2
#define SEQ 2048
#define MROWS (BATCH * SEQ)        // 4096
#define QKV_COLS (3 * EMBED)       // 3072
#define ATT_SCALE 0.125f           // 64^-0.5

// Scratch (allocation-free rule: __device__ globals)
// qkv laid out as [s][b][h][n][d]: s in {q,k,v}
__device__ float g_qkv[3 * BATCH * NHEADS * SEQ * HDIM];
__device__ float g_attn[BATCH * SEQ * EMBED];

// ---------------------------------------------------------------------------
// GEMM 1: qkv = x @ w_qkv + b_qkv, epilogue scatters into [s][b][h][n][d]
// M=4096, N=3072, K=1024. Tile 128x128x16, 256 threads, 8x8 per thread.
// ---------------------------------------------------------------------------
__global__ __launch_bounds__(256, 2)
void qkv_gemm(const float* __restrict__ A,      // x [4096,1024]
              const float* __restrict__ W,      // w_qkv [1024,3072]
              const float* __restrict__ bias)   // [3072]
{
    __shared__ float As[16][132];   // padded: (4k+row)%32 distinct per store group
    __shared__ float Bs[16][128];

    const int K = EMBED;
    const int NC = QKV_COLS;
    const int tid = threadIdx.x;
    const int m0 = blockIdx.y * 128;
    const int n0 = blockIdx.x * 128;
    const int tx = tid & 15;
    const int ty = tid >> 4;

    float acc[8][8];
#pragma unroll
    for (int i = 0; i < 8; i++)
#pragma unroll
        for (int j = 0; j < 8; j++) acc[i][j] = 0.f;

    for (int k0 = 0; k0 < K; k0 += 16) {
        // A tile: 128 rows x 16 cols -> store transposed As[k][m]
#pragma unroll
        for (int i = 0; i < 2; i++) {
            int idx = tid + i * 256;          // 0..511
            int row = idx >> 2;               // 0..127
            int c4 = idx & 3;                 // 0..3
            float4 v = *(const float4*)&A[(size_t)(m0 + row) * K + k0 + c4 * 4];
            As[c4 * 4 + 0][row] = v.x;
            As[c4 * 4 + 1][row] = v.y;
            As[c4 * 4 + 2][row] = v.z;
            As[c4 * 4 + 3][row] = v.w;
        }
        // B tile: 16 rows x 128 cols
#pragma unroll
        for (int i = 0; i < 2; i++) {
            int idx = tid + i * 256;
            int row = idx >> 5;               // 0..15
            int c4 = idx & 31;                // 0..31
            *(float4*)&Bs[row][c4 * 4] =
                *(const float4*)&W[(size_t)(k0 + row) * NC + n0 + c4 * 4];
        }
        __syncthreads();

#pragma unroll
        for (int kk = 0; kk < 16; kk++) {
            float a[8], b[8];
            *(float4*)&a[0] = *(const float4*)&As[kk][ty * 8];
            *(float4*)&a[4] = *(const float4*)&As[kk][ty * 8 + 4];
            *(float4*)&b[0] = *(const float4*)&Bs[kk][tx * 8];
            *(float4*)&b[4] = *(const float4*)&Bs[kk][tx * 8 + 4];
#pragma unroll
            for (int i = 0; i < 8; i++)
#pragma unroll
                for (int j = 0; j < 8; j++)
                    acc[i][j] = fmaf(a[i], b[j], acc[i][j]);
        }
        __syncthreads();
    }

    // Epilogue: add bias, scatter to [s][b][h][n][d]
#pragma unroll
    for (int i = 0; i < 8; i++) {
        int m = m0 + ty * 8 + i;
        int b = m >> 11;            // /2048
        int n = m & 2047;
#pragma unroll
        for (int j = 0; j < 8; j++) {
            int jc = n0 + tx * 8 + j;
            float v = acc[i][j] + bias[jc];
            int s = jc >> 10;
            int rem = jc & 1023;
            int h = rem >> 6;
            int d = rem & 63;
            g_qkv[(((size_t)((s * BATCH + b) * NHEADS + h)) * SEQ + n) * HDIM + d] = v;
        }
    }
}

// ---------------------------------------------------------------------------
// Flash attention, fp32. One query row per thread (128 rows/block).
// grid = (SEQ/128, B*H). K/V tiles of 16 rows in smem, broadcast reads.
// ---------------------------------------------------------------------------
#define BN_KV 16

__global__ __launch_bounds__(128)
void attn_kernel()
{
    __shared__ float Ks[BN_KV][HDIM];
    __shared__ float Vs[BN_KV][HDIM];

    const int tid = threadIdx.x;            // 0..127
    const int bh = blockIdx.y;               // 0..31  (b*16 + h)
    const int r = blockIdx.x * 128 + tid;    // query row in [0,2048)

    const float* Qp = g_qkv + ((size_t)(0 * BATCH * NHEADS + bh) * SEQ + r) * HDIM;
    const float* Kb = g_qkv + ((size_t)(1 * BATCH * NHEADS + bh) * SEQ) * HDIM;
    const float* Vb = g_qkv + ((size_t)(2 * BATCH * NHEADS + bh) * SEQ) * HDIM;

    float4 q[16];
#pragma unroll
    for (int i = 0; i < 16; i++) {
        q[i] = ((const float4*)Qp)[i];
        q[i].x *= ATT_SCALE; q[i].y *= ATT_SCALE;
        q[i].z *= ATT_SCALE; q[i].w *= ATT_SCALE;
    }

    float4 o[16];
#pragma unroll
    for (int i = 0; i < 16; i++) o[i] = make_float4(0.f, 0.f, 0.f, 0.f);
    float mi = -INFINITY, li = 0.f;

    for (int t = 0; t < SEQ; t += BN_KV) {
        // load K,V tile: 16x64 floats each = 256 float4, 128 threads -> 2 each
#pragma unroll
        for (int i = 0; i < 2; i++) {
            int idx = tid + i * 128;          // 0..255
            int row = idx >> 4;               // 0..15
            int c4 = idx & 15;                // 0..15
            *(float4*)&Ks[row][c4 * 4] = *(const float4*)&Kb[(size_t)(t + row) * HDIM + c4 * 4];
            *(float4*)&Vs[row][c4 * 4] = *(const float4*)&Vb[(size_t)(t + row) * HDIM + c4 * 4];
        }
        __syncthreads();

        float sv[BN_KV];
        float tmax = mi;
#pragma unroll
        for (int j = 0; j < BN_KV; j++) {
            float s = 0.f;
#pragma unroll
            for (int d4 = 0; d4 < 16; d4++) {
                float4 kv = *(const float4*)&Ks[j][d4 * 4];
                s = fmaf(q[d4].x, kv.x, s);
                s = fmaf(q[d4].y, kv.y, s);
                s = fmaf(q[d4].z, kv.z, s);
                s = fmaf(q[d4].w, kv.w, s);
            }
            sv[j] = s;
            tmax = fmaxf(tmax, s);
        }

        float corr = __expf(mi - tmax);       // mi=-inf on first tile -> 0
        li *= corr;
#pragma unroll
        for (int i = 0; i < 16; i++) {
            o[i].x *= corr; o[i].y *= corr; o[i].z *= corr; o[i].w *= corr;
        }
#pragma unroll
        for (int j = 0; j < BN_KV; j++) {
            float p = __expf(sv[j] - tmax);
            li += p;
#pragma unroll
            for (int d4 = 0; d4 < 16; d4++) {
                float4 vv = *(const float4*)&Vs[j][d4 * 4];
                o[d4].x = fmaf(p, vv.x, o[d4].x);
                o[d4].y = fmaf(p, vv.y, o[d4].y);
                o[d4].z = fmaf(p, vv.z, o[d4].z);
                o[d4].w = fmaf(p, vv.w, o[d4].w);
            }
        }
        mi = tmax;
        __syncthreads();
    }

    float inv = 1.f / li;
    int b = bh >> 4;
    int h = bh & 15;
    float* op = g_attn + ((size_t)(b * SEQ + r)) * EMBED + h * HDIM;
#pragma unroll
    for (int i = 0; i < 16; i++) {
        float4 v = o[i];
        v.x *= inv; v.y *= inv; v.z *= inv; v.w *= inv;
        ((float4*)op)[i] = v;
    }
}

// ---------------------------------------------------------------------------
// GEMM 2: out = attn @ w_proj + b_proj. M=4096, N=1024, K=1024.
// ---------------------------------------------------------------------------
__global__ __launch_bounds__(256, 2)
void proj_gemm(const float* __restrict__ W,      // w_proj [1024,1024]
               const float* __restrict__ bias,   // [1024]
               float* __restrict__ C)            // [4096,1024]
{
    __shared__ float As[16][132];
    __shared__ float Bs[16][128];

    const int K = EMBED;
    const int NC = EMBED;
    const int tid = threadIdx.x;
    const int m0 = blockIdx.y * 128;
    const int n0 = blockIdx.x * 128;
    const int tx = tid & 15;
    const int ty = tid >> 4;

    float acc[8][8];
#pragma unroll
    for (int i = 0; i < 8; i++)
#pragma unroll
        for (int j = 0; j < 8; j++) acc[i][j] = 0.f;

    const float* A = g_attn;

    for (int k0 = 0; k0 < K; k0 += 16) {
#pragma unroll
        for (int i = 0; i < 2; i++) {
            int idx = tid + i * 256;
            int row = idx >> 2;
            int c4 = idx & 3;
            float4 v = *(const float4*)&A[(size_t)(m0 + row) * K + k0 + c4 * 4];
            As[c4 * 4 + 0][row] = v.x;
            As[c4 * 4 + 1][row] = v.y;
            As[c4 * 4 + 2][row] = v.z;
            As[c4 * 4 + 3][row] = v.w;
        }
#pragma unroll
        for (int i = 0; i < 2; i++) {
            int idx = tid + i * 256;
            int row = idx >> 5;
            int c4 = idx & 31;
            *(float4*)&Bs[row][c4 * 4] =
                *(const float4*)&W[(size_t)(k0 + row) * NC + n0 + c4 * 4];
        }
        __syncthreads();

#pragma unroll
        for (int kk = 0; kk < 16; kk++) {
            float a[8], b[8];
            *(float4*)&a[0] = *(const float4*)&As[kk][ty * 8];
            *(float4*)&a[4] = *(const float4*)&As[kk][ty * 8 + 4];
            *(float4*)&b[0] = *(const float4*)&Bs[kk][tx * 8];
            *(float4*)&b[4] = *(const float4*)&Bs[kk][tx * 8 + 4];
#pragma unroll
            for (int i = 0; i < 8; i++)
#pragma unroll
                for (int j = 0; j < 8; j++)
                    acc[i][j] = fmaf(a[i], b[j], acc[i][j]);
        }
        __syncthreads();
    }

#pragma unroll
    for (int i = 0; i < 8; i++) {
        int m = m0 + ty * 8 + i;
#pragma unroll
        for (int j = 0; j < 8; j += 4) {
            int jc = n0 + tx * 8 + j;
            float4 v;
            v.x = acc[i][j + 0] + bias[jc + 0];
            v.y = acc[i][j + 1] + bias[jc + 1];
            v.z = acc[i][j + 2] + bias[jc + 2];
            v.w = acc[i][j + 3] + bias[jc + 3];
            *(float4*)&C[(size_t)m * NC + jc] = v;
        }
    }
}

// ---------------------------------------------------------------------------
extern "C" void kernel_launch(void* const* d_in, const int* in_sizes, int n_in,
                              void* d_out, int out_size)
{
    const float* x      = (const float*)d_in[0];
    const float* w_qkv  = (const float*)d_in[1];
    const float* b_qkv  = (const float*)d_in[2];
    const float* w_proj = (const float*)d_in[3];
    const float* b_proj = (const float*)d_in[4];
    float* out = (float*)d_out;

    dim3 g1(QKV_COLS / 128, MROWS / 128);   // (24, 32)
    qkv_gemm<<<g1, 256>>>(x, w_qkv, b_qkv);

    dim3 g2(SEQ / 128, BATCH * NHEADS);     // (16, 32)
    attn_kernel<<<g2, 128>>>();

    dim3 g3(EMBED / 128, MROWS / 128);      // (8, 32)
    proj_gemm<<<g3, 256>>>(w_proj, b_proj, out);
}

// round 10
// speedup vs baseline: 1.1238x; 1.1238x over previous
#include <cuda_runtime.h>
#include <cuda_bf16.h>
#include <math.h>

// Problem constants
#define EMBED 1024
#define NHEADS 16
#define HDIM 64
#define BATCH 2
#define SEQ 2048
#define MROWS (BATCH * SEQ)        // 4096
#define QKV_COLS (3 * EMBED)       // 3072
#define ATT_SCALE 0.125f           // 64^-0.5

// Scratch (allocation-free rule: __device__ globals)
// qkv laid out as [s][b][h][n][d]: s in {q,k,v}
__device__ float g_qkv[3 * BATCH * NHEADS * SEQ * HDIM];
__device__ float g_attn[BATCH * SEQ * EMBED];

// ---------------------------------------------------------------------------
// GEMM 1: qkv = x @ w_qkv + b_qkv, epilogue scatters into [s][b][h][n][d]
// M=4096, N=3072, K=1024. Tile 128x128x16, 256 threads, 8x8 per thread.
// ---------------------------------------------------------------------------
__global__ __launch_bounds__(256, 2)
void qkv_gemm(const float* __restrict__ A,      // x [4096,1024]
              const float* __restrict__ W,      // w_qkv [1024,3072]
              const float* __restrict__ bias)   // [3072]
{
    __shared__ float As[16][132];   // padded
    __shared__ float Bs[16][128];

    const int K = EMBED;
    const int NC = QKV_COLS;
    const int tid = threadIdx.x;
    const int m0 = blockIdx.y * 128;
    const int n0 = blockIdx.x * 128;
    const int tx = tid & 15;
    const int ty = tid >> 4;

    float acc[8][8];
#pragma unroll
    for (int i = 0; i < 8; i++)
#pragma unroll
        for (int j = 0; j < 8; j++) acc[i][j] = 0.f;

    for (int k0 = 0; k0 < K; k0 += 16) {
        // A tile: 128 rows x 16 cols -> store transposed As[k][m]
#pragma unroll
        for (int i = 0; i < 2; i++) {
            int idx = tid + i * 256;          // 0..511
            int row = idx >> 2;               // 0..127
            int c4 = idx & 3;                 // 0..3
            float4 v = *(const float4*)&A[(size_t)(m0 + row) * K + k0 + c4 * 4];
            As[c4 * 4 + 0][row] = v.x;
            As[c4 * 4 + 1][row] = v.y;
            As[c4 * 4 + 2][row] = v.z;
            As[c4 * 4 + 3][row] = v.w;
        }
        // B tile: 16 rows x 128 cols
#pragma unroll
        for (int i = 0; i < 2; i++) {
            int idx = tid + i * 256;
            int row = idx >> 5;               // 0..15
            int c4 = idx & 31;                // 0..31
            *(float4*)&Bs[row][c4 * 4] =
                *(const float4*)&W[(size_t)(k0 + row) * NC + n0 + c4 * 4];
        }
        __syncthreads();

#pragma unroll
        for (int kk = 0; kk < 16; kk++) {
            float a[8], b[8];
            *(float4*)&a[0] = *(const float4*)&As[kk][ty * 8];
            *(float4*)&a[4] = *(const float4*)&As[kk][ty * 8 + 4];
            *(float4*)&b[0] = *(const float4*)&Bs[kk][tx * 8];
            *(float4*)&b[4] = *(const float4*)&Bs[kk][tx * 8 + 4];
#pragma unroll
            for (int i = 0; i < 8; i++)
#pragma unroll
                for (int j = 0; j < 8; j++)
                    acc[i][j] = fmaf(a[i], b[j], acc[i][j]);
        }
        __syncthreads();
    }

    // Epilogue: add bias, scatter to [s][b][h][n][d]
#pragma unroll
    for (int i = 0; i < 8; i++) {
        int m = m0 + ty * 8 + i;
        int b = m >> 11;            // /2048
        int n = m & 2047;
#pragma unroll
        for (int j = 0; j < 8; j++) {
            int jc = n0 + tx * 8 + j;
            float v = acc[i][j] + bias[jc];
            int s = jc >> 10;
            int rem = jc & 1023;
            int h = rem >> 6;
            int d = rem & 63;
            g_qkv[(((size_t)((s * BATCH + b) * NHEADS + h)) * SEQ + n) * HDIM + d] = v;
        }
    }
}

// ---------------------------------------------------------------------------
// Flash attention, fp32. One query row per thread (128 rows/block).
// grid = (SEQ/128, B*H). K/V tiles of 32 rows in smem, broadcast reads.
// (Identical structure to the round-1 passing kernel; BN_KV 16 -> 32 to
//  halve the barrier count.)
// ---------------------------------------------------------------------------
#define BN_KV 32

__global__ __launch_bounds__(128)
void attn_kernel()
{
    __shared__ float Ks[BN_KV][HDIM];
    __shared__ float Vs[BN_KV][HDIM];

    const int tid = threadIdx.x;            // 0..127
    const int bh = blockIdx.y;               // 0..31  (b*16 + h)
    const int r = blockIdx.x * 128 + tid;    // query row in [0,2048)

    const float* Qp = g_qkv + ((size_t)(0 * BATCH * NHEADS + bh) * SEQ + r) * HDIM;
    const float* Kb = g_qkv + ((size_t)(1 * BATCH * NHEADS + bh) * SEQ) * HDIM;
    const float* Vb = g_qkv + ((size_t)(2 * BATCH * NHEADS + bh) * SEQ) * HDIM;

    float4 q[16];
#pragma unroll
    for (int i = 0; i < 16; i++) {
        q[i] = ((const float4*)Qp)[i];
        q[i].x *= ATT_SCALE; q[i].y *= ATT_SCALE;
        q[i].z *= ATT_SCALE; q[i].w *= ATT_SCALE;
    }

    float4 o[16];
#pragma unroll
    for (int i = 0; i < 16; i++) o[i] = make_float4(0.f, 0.f, 0.f, 0.f);
    float mi = -INFINITY, li = 0.f;

    for (int t = 0; t < SEQ; t += BN_KV) {
        // load K,V tile: 32x64 floats each = 512 float4, 128 threads -> 4 each
#pragma unroll
        for (int i = 0; i < 4; i++) {
            int idx = tid + i * 128;          // 0..511
            int row = idx >> 4;               // 0..31
            int c4 = idx & 15;                // 0..15
            *(float4*)&Ks[row][c4 * 4] = *(const float4*)&Kb[(size_t)(t + row) * HDIM + c4 * 4];
            *(float4*)&Vs[row][c4 * 4] = *(const float4*)&Vb[(size_t)(t + row) * HDIM + c4 * 4];
        }
        __syncthreads();

        float sv[BN_KV];
        float tmax = mi;
#pragma unroll
        for (int j = 0; j < BN_KV; j++) {
            float s = 0.f;
#pragma unroll
            for (int d4 = 0; d4 < 16; d4++) {
                float4 kv = *(const float4*)&Ks[j][d4 * 4];
                s = fmaf(q[d4].x, kv.x, s);
                s = fmaf(q[d4].y, kv.y, s);
                s = fmaf(q[d4].z, kv.z, s);
                s = fmaf(q[d4].w, kv.w, s);
            }
            sv[j] = s;
            tmax = fmaxf(tmax, s);
        }

        float corr = __expf(mi - tmax);       // mi=-inf on first tile -> 0
        li *= corr;
#pragma unroll
        for (int i = 0; i < 16; i++) {
            o[i].x *= corr; o[i].y *= corr; o[i].z *= corr; o[i].w *= corr;
        }
#pragma unroll
        for (int j = 0; j < BN_KV; j++) {
            float p = __expf(sv[j] - tmax);
            li += p;
#pragma unroll
            for (int d4 = 0; d4 < 16; d4++) {
                float4 vv = *(const float4*)&Vs[j][d4 * 4];
                o[d4].x = fmaf(p, vv.x, o[d4].x);
                o[d4].y = fmaf(p, vv.y, o[d4].y);
                o[d4].z = fmaf(p, vv.z, o[d4].z);
                o[d4].w = fmaf(p, vv.w, o[d4].w);
            }
        }
        mi = tmax;
        __syncthreads();
    }

    float inv = 1.f / li;
    int b = bh >> 4;
    int h = bh & 15;
    float* op = g_attn + ((size_t)(b * SEQ + r)) * EMBED + h * HDIM;
#pragma unroll
    for (int i = 0; i < 16; i++) {
        float4 v = o[i];
        v.x *= inv; v.y *= inv; v.z *= inv; v.w *= inv;
        ((float4*)op)[i] = v;
    }
}

// ---------------------------------------------------------------------------
// GEMM 2: out = attn @ w_proj + b_proj. M=4096, N=1024, K=1024.
// ---------------------------------------------------------------------------
__global__ __launch_bounds__(256, 2)
void proj_gemm(const float* __restrict__ W,      // w_proj [1024,1024]
               const float* __restrict__ bias,   // [1024]
               float* __restrict__ C)            // [4096,1024]
{
    __shared__ float As[16][132];
    __shared__ float Bs[16][128];

    const int K = EMBED;
    const int NC = EMBED;
    const int tid = threadIdx.x;
    const int m0 = blockIdx.y * 128;
    const int n0 = blockIdx.x * 128;
    const int tx = tid & 15;
    const int ty = tid >> 4;

    float acc[8][8];
#pragma unroll
    for (int i = 0; i < 8; i++)
#pragma unroll
        for (int j = 0; j < 8; j++) acc[i][j] = 0.f;

    const float* A = g_attn;

    for (int k0 = 0; k0 < K; k0 += 16) {
#pragma unroll
        for (int i = 0; i < 2; i++) {
            int idx = tid + i * 256;
            int row = idx >> 2;
            int c4 = idx & 3;
            float4 v = *(const float4*)&A[(size_t)(m0 + row) * K + k0 + c4 * 4];
            As[c4 * 4 + 0][row] = v.x;
            As[c4 * 4 + 1][row] = v.y;
            As[c4 * 4 + 2][row] = v.z;
            As[c4 * 4 + 3][row] = v.w;
        }
#pragma unroll
        for (int i = 0; i < 2; i++) {
            int idx = tid + i * 256;
            int row = idx >> 5;
            int c4 = idx & 31;
            *(float4*)&Bs[row][c4 * 4] =
                *(const float4*)&W[(size_t)(k0 + row) * NC + n0 + c4 * 4];
        }
        __syncthreads();

#pragma unroll
        for (int kk = 0; kk < 16; kk++) {
            float a[8], b[8];
            *(float4*)&a[0] = *(const float4*)&As[kk][ty * 8];
            *(float4*)&a[4] = *(const float4*)&As[kk][ty * 8 + 4];
            *(float4*)&b[0] = *(const float4*)&Bs[kk][tx * 8];
            *(float4*)&b[4] = *(const float4*)&Bs[kk][tx * 8 + 4];
#pragma unroll
            for (int i = 0; i < 8; i++)
#pragma unroll
                for (int j = 0; j < 8; j++)
                    acc[i][j] = fmaf(a[i], b[j], acc[i][j]);
        }
        __syncthreads();
    }

#pragma unroll
    for (int i = 0; i < 8; i++) {
        int m = m0 + ty * 8 + i;
#pragma unroll
        for (int j = 0; j < 8; j += 4) {
            int jc = n0 + tx * 8 + j;
            float4 v;
            v.x = acc[i][j + 0] + bias[jc + 0];
            v.y = acc[i][j + 1] + bias[jc + 1];
            v.z = acc[i][j + 2] + bias[jc + 2];
            v.w = acc[i][j + 3] + bias[jc + 3];
            *(float4*)&C[(size_t)m * NC + jc] = v;
        }
    }
}

// ---------------------------------------------------------------------------
extern "C" void kernel_launch(void* const* d_in, const int* in_sizes, int n_in,
                              void* d_out, int out_size)
{
    const float* x      = (const float*)d_in[0];
    const float* w_qkv  = (const float*)d_in[1];
    const float* b_qkv  = (const float*)d_in[2];
    const float* w_proj = (const float*)d_in[3];
    const float* b_proj = (const float*)d_in[4];
    float* out = (float*)d_out;

    dim3 g1(QKV_COLS / 128, MROWS / 128);   // (24, 32)
    qkv_gemm<<<g1, 256>>>(x, w_qkv, b_qkv);

    dim3 g2(SEQ / 128, BATCH * NHEADS);     // (16, 32)
    attn_kernel<<<g2, 128>>>();

    dim3 g3(EMBED / 128, MROWS / 128);      // (8, 32)
    proj_gemm<<<g3, 256>>>(w_proj, b_proj, out);
}

// round 11
// speedup vs baseline: 1.1434x; 1.0175x over previous
#include <cuda_runtime.h>
#include <cuda_bf16.h>
#include <math.h>

// Problem constants
#define EMBED 1024
#define NHEADS 16
#define HDIM 64
#define BATCH 2
#define SEQ 2048
#define MROWS (BATCH * SEQ)        // 4096
#define QKV_COLS (3 * EMBED)       // 3072
#define ATT_SCALE 0.125f           // 64^-0.5

// Scratch (allocation-free rule: __device__ globals)
// qkv laid out as [s][b][h][n][d]: s in {q,k,v}
__device__ float g_qkv[3 * BATCH * NHEADS * SEQ * HDIM];
__device__ float g_attn[BATCH * SEQ * EMBED];

// ---------------------------------------------------------------------------
// GEMM 1: qkv = x @ w_qkv + b_qkv, epilogue scatters into [s][b][h][n][d]
// M=4096, N=3072, K=1024. Tile 128x128x16, 256 threads, 8x8 per thread.
// Double-buffered smem + register prefetch: ONE barrier per k-chunk.
// ---------------------------------------------------------------------------
__global__ __launch_bounds__(256, 2)
void qkv_gemm(const float* __restrict__ A,      // x [4096,1024]
              const float* __restrict__ W,      // w_qkv [1024,3072]
              const float* __restrict__ bias)   // [3072]
{
    __shared__ float As[2][16][132];   // transposed A, padded
    __shared__ float Bs[2][16][128];

    const int K = EMBED;
    const int NC = QKV_COLS;
    const int tid = threadIdx.x;
    const int m0 = blockIdx.y * 128;
    const int n0 = blockIdx.x * 128;
    const int tx = tid & 15;
    const int ty = tid >> 4;

    // per-thread load geometry (2 float4 for A, 2 for B)
    const int arow0 = tid >> 2, ac4 = tid & 3;
    const int arow1 = arow0 + 64;
    const int brow0 = tid >> 5, bc4 = tid & 31;
    const int brow1 = brow0 + 8;

    float acc[8][8];
#pragma unroll
    for (int i = 0; i < 8; i++)
#pragma unroll
        for (int j = 0; j < 8; j++) acc[i][j] = 0.f;

    float4 ra0, ra1, rb0, rb1;
    ra0 = *(const float4*)&A[(size_t)(m0 + arow0) * K + ac4 * 4];
    ra1 = *(const float4*)&A[(size_t)(m0 + arow1) * K + ac4 * 4];
    rb0 = *(const float4*)&W[(size_t)brow0 * NC + n0 + bc4 * 4];
    rb1 = *(const float4*)&W[(size_t)brow1 * NC + n0 + bc4 * 4];

    for (int i = 0; i < K / 16; i++) {
        const int s = i & 1;

        As[s][ac4 * 4 + 0][arow0] = ra0.x;
        As[s][ac4 * 4 + 1][arow0] = ra0.y;
        As[s][ac4 * 4 + 2][arow0] = ra0.z;
        As[s][ac4 * 4 + 3][arow0] = ra0.w;
        As[s][ac4 * 4 + 0][arow1] = ra1.x;
        As[s][ac4 * 4 + 1][arow1] = ra1.y;
        As[s][ac4 * 4 + 2][arow1] = ra1.z;
        As[s][ac4 * 4 + 3][arow1] = ra1.w;
        *(float4*)&Bs[s][brow0][bc4 * 4] = rb0;
        *(float4*)&Bs[s][brow1][bc4 * 4] = rb1;

        if (i + 1 < K / 16) {
            int k0 = (i + 1) * 16;
            ra0 = *(const float4*)&A[(size_t)(m0 + arow0) * K + k0 + ac4 * 4];
            ra1 = *(const float4*)&A[(size_t)(m0 + arow1) * K + k0 + ac4 * 4];
            rb0 = *(const float4*)&W[(size_t)(k0 + brow0) * NC + n0 + bc4 * 4];
            rb1 = *(const float4*)&W[(size_t)(k0 + brow1) * NC + n0 + bc4 * 4];
        }

        __syncthreads();   // single barrier per chunk (double-buffered)

#pragma unroll
        for (int kk = 0; kk < 16; kk++) {
            float a[8], b[8];
            *(float4*)&a[0] = *(const float4*)&As[s][kk][ty * 8];
            *(float4*)&a[4] = *(const float4*)&As[s][kk][ty * 8 + 4];
            *(float4*)&b[0] = *(const float4*)&Bs[s][kk][tx * 8];
            *(float4*)&b[4] = *(const float4*)&Bs[s][kk][tx * 8 + 4];
#pragma unroll
            for (int ii = 0; ii < 8; ii++)
#pragma unroll
                for (int jj = 0; jj < 8; jj++)
                    acc[ii][jj] = fmaf(a[ii], b[jj], acc[ii][jj]);
        }
    }

    // Epilogue: add bias, scatter to [s][b][h][n][d] with float4 stores.
    // jc = n0 + tx*8 + j, j=0..7 all share the same (s,h) and d is 8-aligned.
    {
        int jc0 = n0 + tx * 8;
        int sI = jc0 >> 10;
        int rem = jc0 & 1023;
        int h = rem >> 6;
        int d = rem & 63;
        float b0 = bias[jc0 + 0], b1 = bias[jc0 + 1], b2 = bias[jc0 + 2], b3 = bias[jc0 + 3];
        float b4 = bias[jc0 + 4], b5 = bias[jc0 + 5], b6 = bias[jc0 + 6], b7 = bias[jc0 + 7];
#pragma unroll
        for (int i = 0; i < 8; i++) {
            int m = m0 + ty * 8 + i;
            int b = m >> 11;
            int n = m & 2047;
            float* dst = &g_qkv[(((size_t)((sI * BATCH + b) * NHEADS + h)) * SEQ + n) * HDIM + d];
            float4 v0, v1;
            v0.x = acc[i][0] + b0; v0.y = acc[i][1] + b1;
            v0.z = acc[i][2] + b2; v0.w = acc[i][3] + b3;
            v1.x = acc[i][4] + b4; v1.y = acc[i][5] + b5;
            v1.z = acc[i][6] + b6; v1.w = acc[i][7] + b7;
            *(float4*)dst = v0;
            *(float4*)(dst + 4) = v1;
        }
    }
}

// ---------------------------------------------------------------------------
// Flash attention, fp32. One query row per thread (128 rows/block).
// K/V tiles of 32 rows, DOUBLE-BUFFERED + register prefetch: 1 barrier/tile.
// ---------------------------------------------------------------------------
#define BN_KV 32

__global__ __launch_bounds__(128)
void attn_kernel()
{
    __shared__ float Ks[2][BN_KV][HDIM];
    __shared__ float Vs[2][BN_KV][HDIM];

    const int tid = threadIdx.x;            // 0..127
    const int bh = blockIdx.y;               // 0..31  (b*16 + h)
    const int r = blockIdx.x * 128 + tid;    // query row in [0,2048)

    const float* Qp = g_qkv + ((size_t)(0 * BATCH * NHEADS + bh) * SEQ + r) * HDIM;
    const float* Kb = g_qkv + ((size_t)(1 * BATCH * NHEADS + bh) * SEQ) * HDIM;
    const float* Vb = g_qkv + ((size_t)(2 * BATCH * NHEADS + bh) * SEQ) * HDIM;

    float4 q[16];
#pragma unroll
    for (int i = 0; i < 16; i++) {
        q[i] = ((const float4*)Qp)[i];
        q[i].x *= ATT_SCALE; q[i].y *= ATT_SCALE;
        q[i].z *= ATT_SCALE; q[i].w *= ATT_SCALE;
    }

    float4 o[16];
#pragma unroll
    for (int i = 0; i < 16; i++) o[i] = make_float4(0.f, 0.f, 0.f, 0.f);
    float mi = -INFINITY, li = 0.f;

    // per-thread load geometry: 4 K float4 + 4 V float4 per tile
    const int lrow = tid >> 4;          // 0..7
    const int lc4 = tid & 15;           // 0..15

    float4 pk[4], pv[4];
#pragma unroll
    for (int u = 0; u < 4; u++) {
        pk[u] = *(const float4*)&Kb[(size_t)(u * 8 + lrow) * HDIM + lc4 * 4];
        pv[u] = *(const float4*)&Vb[(size_t)(u * 8 + lrow) * HDIM + lc4 * 4];
    }

    for (int t = 0; t < SEQ / BN_KV; t++) {
        const int s = t & 1;

#pragma unroll
        for (int u = 0; u < 4; u++) {
            *(float4*)&Ks[s][u * 8 + lrow][lc4 * 4] = pk[u];
            *(float4*)&Vs[s][u * 8 + lrow][lc4 * 4] = pv[u];
        }

        if (t + 1 < SEQ / BN_KV) {
            int kb = (t + 1) * BN_KV;
#pragma unroll
            for (int u = 0; u < 4; u++) {
                pk[u] = *(const float4*)&Kb[(size_t)(kb + u * 8 + lrow) * HDIM + lc4 * 4];
                pv[u] = *(const float4*)&Vb[(size_t)(kb + u * 8 + lrow) * HDIM + lc4 * 4];
            }
        }

        __syncthreads();   // single barrier per tile (double-buffered)

        float sv[BN_KV];
        float tmax = mi;
#pragma unroll
        for (int j = 0; j < BN_KV; j++) {
            float sacc = 0.f;
#pragma unroll
            for (int d4 = 0; d4 < 16; d4++) {
                float4 kv = *(const float4*)&Ks[s][j][d4 * 4];
                sacc = fmaf(q[d4].x, kv.x, sacc);
                sacc = fmaf(q[d4].y, kv.y, sacc);
                sacc = fmaf(q[d4].z, kv.z, sacc);
                sacc = fmaf(q[d4].w, kv.w, sacc);
            }
            sv[j] = sacc;
            tmax = fmaxf(tmax, sacc);
        }

        float corr = __expf(mi - tmax);       // mi=-inf on first tile -> 0
        li *= corr;
#pragma unroll
        for (int i = 0; i < 16; i++) {
            o[i].x *= corr; o[i].y *= corr; o[i].z *= corr; o[i].w *= corr;
        }
#pragma unroll
        for (int j = 0; j < BN_KV; j++) {
            float p = __expf(sv[j] - tmax);
            li += p;
#pragma unroll
            for (int d4 = 0; d4 < 16; d4++) {
                float4 vv = *(const float4*)&Vs[s][j][d4 * 4];
                o[d4].x = fmaf(p, vv.x, o[d4].x);
                o[d4].y = fmaf(p, vv.y, o[d4].y);
                o[d4].z = fmaf(p, vv.z, o[d4].z);
                o[d4].w = fmaf(p, vv.w, o[d4].w);
            }
        }
        mi = tmax;
    }

    float inv = 1.f / li;
    int b = bh >> 4;
    int h = bh & 15;
    float* op = g_attn + ((size_t)(b * SEQ + r)) * EMBED + h * HDIM;
#pragma unroll
    for (int i = 0; i < 16; i++) {
        float4 v = o[i];
        v.x *= inv; v.y *= inv; v.z *= inv; v.w *= inv;
        ((float4*)op)[i] = v;
    }
}

// ---------------------------------------------------------------------------
// GEMM 2: out = attn @ w_proj + b_proj. M=4096, N=1024, K=1024.
// Same double-buffered structure as qkv_gemm.
// ---------------------------------------------------------------------------
__global__ __launch_bounds__(256, 2)
void proj_gemm(const float* __restrict__ W,      // w_proj [1024,1024]
               const float* __restrict__ bias,   // [1024]
               float* __restrict__ C)            // [4096,1024]
{
    __shared__ float As[2][16][132];
    __shared__ float Bs[2][16][128];

    const int K = EMBED;
    const int NC = EMBED;
    const int tid = threadIdx.x;
    const int m0 = blockIdx.y * 128;
    const int n0 = blockIdx.x * 128;
    const int tx = tid & 15;
    const int ty = tid >> 4;

    const int arow0 = tid >> 2, ac4 = tid & 3;
    const int arow1 = arow0 + 64;
    const int brow0 = tid >> 5, bc4 = tid & 31;
    const int brow1 = brow0 + 8;

    float acc[8][8];
#pragma unroll
    for (int i = 0; i < 8; i++)
#pragma unroll
        for (int j = 0; j < 8; j++) acc[i][j] = 0.f;

    const float* A = g_attn;

    float4 ra0, ra1, rb0, rb1;
    ra0 = *(const float4*)&A[(size_t)(m0 + arow0) * K + ac4 * 4];
    ra1 = *(const float4*)&A[(size_t)(m0 + arow1) * K + ac4 * 4];
    rb0 = *(const float4*)&W[(size_t)brow0 * NC + n0 + bc4 * 4];
    rb1 = *(const float4*)&W[(size_t)brow1 * NC + n0 + bc4 * 4];

    for (int i = 0; i < K / 16; i++) {
        const int s = i & 1;

        As[s][ac4 * 4 + 0][arow0] = ra0.x;
        As[s][ac4 * 4 + 1][arow0] = ra0.y;
        As[s][ac4 * 4 + 2][arow0] = ra0.z;
        As[s][ac4 * 4 + 3][arow0] = ra0.w;
        As[s][ac4 * 4 + 0][arow1] = ra1.x;
        As[s][ac4 * 4 + 1][arow1] = ra1.y;
        As[s][ac4 * 4 + 2][arow1] = ra1.z;
        As[s][ac4 * 4 + 3][arow1] = ra1.w;
        *(float4*)&Bs[s][brow0][bc4 * 4] = rb0;
        *(float4*)&Bs[s][brow1][bc4 * 4] = rb1;

        if (i + 1 < K / 16) {
            int k0 = (i + 1) * 16;
            ra0 = *(const float4*)&A[(size_t)(m0 + arow0) * K + k0 + ac4 * 4];
            ra1 = *(const float4*)&A[(size_t)(m0 + arow1) * K + k0 + ac4 * 4];
            rb0 = *(const float4*)&W[(size_t)(k0 + brow0) * NC + n0 + bc4 * 4];
            rb1 = *(const float4*)&W[(size_t)(k0 + brow1) * NC + n0 + bc4 * 4];
        }

        __syncthreads();

#pragma unroll
        for (int kk = 0; kk < 16; kk++) {
            float a[8], b[8];
            *(float4*)&a[0] = *(const float4*)&As[s][kk][ty * 8];
            *(float4*)&a[4] = *(const float4*)&As[s][kk][ty * 8 + 4];
            *(float4*)&b[0] = *(const float4*)&Bs[s][kk][tx * 8];
            *(float4*)&b[4] = *(const float4*)&Bs[s][kk][tx * 8 + 4];
#pragma unroll
            for (int ii = 0; ii < 8; ii++)
#pragma unroll
                for (int jj = 0; jj < 8; jj++)
                    acc[ii][jj] = fmaf(a[ii], b[jj], acc[ii][jj]);
        }
    }

#pragma unroll
    for (int i = 0; i < 8; i++) {
        int m = m0 + ty * 8 + i;
#pragma unroll
        for (int j = 0; j < 8; j += 4) {
            int jc = n0 + tx * 8 + j;
            float4 v;
            v.x = acc[i][j + 0] + bias[jc + 0];
            v.y = acc[i][j + 1] + bias[jc + 1];
            v.z = acc[i][j + 2] + bias[jc + 2];
            v.w = acc[i][j + 3] + bias[jc + 3];
            *(float4*)&C[(size_t)m * NC + jc] = v;
        }
    }
}

// ---------------------------------------------------------------------------
extern "C" void kernel_launch(void* const* d_in, const int* in_sizes, int n_in,
                              void* d_out, int out_size)
{
    const float* x      = (const float*)d_in[0];
    const float* w_qkv  = (const float*)d_in[1];
    const float* b_qkv  = (const float*)d_in[2];
    const float* w_proj = (const float*)d_in[3];
    const float* b_proj = (const float*)d_in[4];
    float* out = (float*)d_out;

    dim3 g1(QKV_COLS / 128, MROWS / 128);   // (24, 32)
    qkv_gemm<<<g1, 256>>>(x, w_qkv, b_qkv);

    dim3 g2(SEQ / 128, BATCH * NHEADS);     // (16, 32)
    attn_kernel<<<g2, 128>>>();

    dim3 g3(EMBED / 128, MROWS / 128);      // (8, 32)
    proj_gemm<<<g3, 256>>>(w_proj, b_proj, out);
}

// round 12
// speedup vs baseline: 1.2214x; 1.0682x over previous
#include <cuda_runtime.h>
#include <math.h>

// Problem constants
#define EMBED 1024
#define NHEADS 16
#define HDIM 64
#define BATCH 2
#define SEQ 2048
#define MROWS (BATCH * SEQ)        // 4096
#define QKV_COLS (3 * EMBED)       // 3072
#define ATT_SCALE 0.125f           // 64^-0.5

// Scratch (allocation-free rule: __device__ globals)
// qkv laid out as [s][b][h][n][d]: s in {q,k,v}
__device__ float g_qkv[3 * BATCH * NHEADS * SEQ * HDIM];
__device__ float g_attn[BATCH * SEQ * EMBED];

// ---------------------------------------------------------------------------
// Packed f32x2 helpers (Blackwell FFMA2 path; PTX ISA 8.6, base sm_100)
// ---------------------------------------------------------------------------
#define F2FMA(d, a, b) \
    asm("fma.rn.f32x2 %0, %1, %2, %0;" : "+l"(d) : "l"(a), "l"(b))
#define F2MUL(d, a, b) \
    asm("mul.rn.f32x2 %0, %1, %2;" : "=l"(d) : "l"(a), "l"(b))
#define F2MULI(d, b) \
    asm("mul.rn.f32x2 %0, %0, %1;" : "+l"(d) : "l"(b))
#define F2ADDI(d, b) \
    asm("add.rn.f32x2 %0, %0, %1;" : "+l"(d) : "l"(b))
#define PACK2(d, lo, hi) \
    asm("mov.b64 %0, {%1, %2};" : "=l"(d) : "f"(lo), "f"(hi))
#define UNPACK2(lo, hi, v) \
    asm("mov.b64 {%0, %1}, %2;" : "=f"(lo), "=f"(hi) : "l"(v))

// ---------------------------------------------------------------------------
// GEMM 1: qkv = x @ w_qkv + b_qkv, epilogue scatters into [s][b][h][n][d]
// M=4096, N=3072, K=1024. Tile 128x128x16, 256 threads, 8x8 per thread.
// Double-buffered smem + reg prefetch; inner product in packed f32x2.
// ---------------------------------------------------------------------------
__global__ __launch_bounds__(256, 2)
void qkv_gemm(const float* __restrict__ A,      // x [4096,1024]
              const float* __restrict__ W,      // w_qkv [1024,3072]
              const float* __restrict__ bias)   // [3072]
{
    __shared__ float As[2][16][132];   // transposed A, padded
    __shared__ float Bs[2][16][128];

    const int K = EMBED;
    const int NC = QKV_COLS;
    const int tid = threadIdx.x;
    const int m0 = blockIdx.y * 128;
    const int n0 = blockIdx.x * 128;
    const int tx = tid & 15;
    const int ty = tid >> 4;

    const int arow0 = tid >> 2, ac4 = tid & 3;
    const int arow1 = arow0 + 64;
    const int brow0 = tid >> 5, bc4 = tid & 31;
    const int brow1 = brow0 + 8;

    unsigned long long acc2[8][4];   // (col j, col j+1) pairs
#pragma unroll
    for (int i = 0; i < 8; i++)
#pragma unroll
        for (int j = 0; j < 4; j++) acc2[i][j] = 0ULL;

    float4 ra0, ra1, rb0, rb1;
    ra0 = *(const float4*)&A[(size_t)(m0 + arow0) * K + ac4 * 4];
    ra1 = *(const float4*)&A[(size_t)(m0 + arow1) * K + ac4 * 4];
    rb0 = *(const float4*)&W[(size_t)brow0 * NC + n0 + bc4 * 4];
    rb1 = *(const float4*)&W[(size_t)brow1 * NC + n0 + bc4 * 4];

    for (int i = 0; i < K / 16; i++) {
        const int s = i & 1;

        As[s][ac4 * 4 + 0][arow0] = ra0.x;
        As[s][ac4 * 4 + 1][arow0] = ra0.y;
        As[s][ac4 * 4 + 2][arow0] = ra0.z;
        As[s][ac4 * 4 + 3][arow0] = ra0.w;
        As[s][ac4 * 4 + 0][arow1] = ra1.x;
        As[s][ac4 * 4 + 1][arow1] = ra1.y;
        As[s][ac4 * 4 + 2][arow1] = ra1.z;
        As[s][ac4 * 4 + 3][arow1] = ra1.w;
        *(float4*)&Bs[s][brow0][bc4 * 4] = rb0;
        *(float4*)&Bs[s][brow1][bc4 * 4] = rb1;

        if (i + 1 < K / 16) {
            int k0 = (i + 1) * 16;
            ra0 = *(const float4*)&A[(size_t)(m0 + arow0) * K + k0 + ac4 * 4];
            ra1 = *(const float4*)&A[(size_t)(m0 + arow1) * K + k0 + ac4 * 4];
            rb0 = *(const float4*)&W[(size_t)(k0 + brow0) * NC + n0 + bc4 * 4];
            rb1 = *(const float4*)&W[(size_t)(k0 + brow1) * NC + n0 + bc4 * 4];
        }

        __syncthreads();   // single barrier per chunk (double-buffered)

#pragma unroll
        for (int kk = 0; kk < 16; kk++) {
            float a[8];
            *(float4*)&a[0] = *(const float4*)&As[s][kk][ty * 8];
            *(float4*)&a[4] = *(const float4*)&As[s][kk][ty * 8 + 4];
            ulonglong2 b01 = *(const ulonglong2*)&Bs[s][kk][tx * 8];
            ulonglong2 b23 = *(const ulonglong2*)&Bs[s][kk][tx * 8 + 4];
#pragma unroll
            for (int ii = 0; ii < 8; ii++) {
                unsigned long long a2;
                PACK2(a2, a[ii], a[ii]);
                F2FMA(acc2[ii][0], a2, b01.x);
                F2FMA(acc2[ii][1], a2, b01.y);
                F2FMA(acc2[ii][2], a2, b23.x);
                F2FMA(acc2[ii][3], a2, b23.y);
            }
        }
    }

    // Epilogue: unpack, add bias, scatter to [s][b][h][n][d] with float4 pairs
    {
        int jc0 = n0 + tx * 8;
        int sI = jc0 >> 10;
        int rem = jc0 & 1023;
        int h = rem >> 6;
        int d = rem & 63;
        float b0 = bias[jc0 + 0], b1 = bias[jc0 + 1], b2 = bias[jc0 + 2], b3 = bias[jc0 + 3];
        float b4 = bias[jc0 + 4], b5 = bias[jc0 + 5], b6 = bias[jc0 + 6], b7 = bias[jc0 + 7];
#pragma unroll
        for (int i = 0; i < 8; i++) {
            int m = m0 + ty * 8 + i;
            int b = m >> 11;
            int n = m & 2047;
            float c0, c1, c2, c3, c4, c5, c6, c7;
            UNPACK2(c0, c1, acc2[i][0]);
            UNPACK2(c2, c3, acc2[i][1]);
            UNPACK2(c4, c5, acc2[i][2]);
            UNPACK2(c6, c7, acc2[i][3]);
            float* dst = &g_qkv[(((size_t)((sI * BATCH + b) * NHEADS + h)) * SEQ + n) * HDIM + d];
            float4 v0, v1;
            v0.x = c0 + b0; v0.y = c1 + b1; v0.z = c2 + b2; v0.w = c3 + b3;
            v1.x = c4 + b4; v1.y = c5 + b5; v1.z = c6 + b6; v1.w = c7 + b7;
            *(float4*)dst = v0;
            *(float4*)(dst + 4) = v1;
        }
    }
}

// ---------------------------------------------------------------------------
// Flash attention, fp32 via packed f32x2. One query row per thread.
// K/V tiles of 32 rows, double-buffered, 1 barrier/tile.
// ---------------------------------------------------------------------------
#define BN_KV 32

__global__ __launch_bounds__(128)
void attn_kernel()
{
    __shared__ float Ks[2][BN_KV][HDIM];
    __shared__ float Vs[2][BN_KV][HDIM];

    const int tid = threadIdx.x;            // 0..127
    const int bh = blockIdx.y;               // 0..31
    const int r = blockIdx.x * 128 + tid;    // query row

    const float* Qp = g_qkv + ((size_t)(0 * BATCH * NHEADS + bh) * SEQ + r) * HDIM;
    const float* Kb = g_qkv + ((size_t)(1 * BATCH * NHEADS + bh) * SEQ) * HDIM;
    const float* Vb = g_qkv + ((size_t)(2 * BATCH * NHEADS + bh) * SEQ) * HDIM;

    // q as 32 packed pairs, pre-scaled
    unsigned long long q2[32];
    {
        unsigned long long sc2;
        PACK2(sc2, ATT_SCALE, ATT_SCALE);
        const ulonglong2* Qp2 = (const ulonglong2*)Qp;
#pragma unroll
        for (int i = 0; i < 16; i++) {
            ulonglong2 tq = Qp2[i];
            F2MUL(q2[2 * i],     tq.x, sc2);
            F2MUL(q2[2 * i + 1], tq.y, sc2);
        }
    }

    unsigned long long o2[32];
#pragma unroll
    for (int i = 0; i < 32; i++) o2[i] = 0ULL;
    float mi = -INFINITY, li = 0.f;

    // per-thread load geometry: 4 K float4 + 4 V float4 per tile
    const int lrow = tid >> 4;          // 0..7
    const int lc4 = tid & 15;           // 0..15

    float4 pk[4], pv[4];
#pragma unroll
    for (int u = 0; u < 4; u++) {
        pk[u] = *(const float4*)&Kb[(size_t)(u * 8 + lrow) * HDIM + lc4 * 4];
        pv[u] = *(const float4*)&Vb[(size_t)(u * 8 + lrow) * HDIM + lc4 * 4];
    }

    for (int t = 0; t < SEQ / BN_KV; t++) {
        const int s = t & 1;

#pragma unroll
        for (int u = 0; u < 4; u++) {
            *(float4*)&Ks[s][u * 8 + lrow][lc4 * 4] = pk[u];
            *(float4*)&Vs[s][u * 8 + lrow][lc4 * 4] = pv[u];
        }

        if (t + 1 < SEQ / BN_KV) {
            int kb = (t + 1) * BN_KV;
#pragma unroll
            for (int u = 0; u < 4; u++) {
                pk[u] = *(const float4*)&Kb[(size_t)(kb + u * 8 + lrow) * HDIM + lc4 * 4];
                pv[u] = *(const float4*)&Vb[(size_t)(kb + u * 8 + lrow) * HDIM + lc4 * 4];
            }
        }

        __syncthreads();   // single barrier per tile (double-buffered)

        // S = q . K_j  (packed pairs, 4 accumulation chains)
        float sv[BN_KV];
        float tmax = mi;
#pragma unroll
        for (int j = 0; j < BN_KV; j++) {
            unsigned long long c0 = 0ULL, c1 = 0ULL, c2 = 0ULL, c3 = 0ULL;
#pragma unroll
            for (int d4 = 0; d4 < 16; d4 += 2) {
                ulonglong2 k0 = *(const ulonglong2*)&Ks[s][j][d4 * 4];
                ulonglong2 k1 = *(const ulonglong2*)&Ks[s][j][d4 * 4 + 4];
                F2FMA(c0, q2[2 * d4],     k0.x);
                F2FMA(c1, q2[2 * d4 + 1], k0.y);
                F2FMA(c2, q2[2 * d4 + 2], k1.x);
                F2FMA(c3, q2[2 * d4 + 3], k1.y);
            }
            F2ADDI(c0, c2);
            F2ADDI(c1, c3);
            F2ADDI(c0, c1);
            float lo, hi;
            UNPACK2(lo, hi, c0);
            float sj = lo + hi;
            sv[j] = sj;
            tmax = fmaxf(tmax, sj);
        }

        float corr = __expf(mi - tmax);       // mi=-inf on first tile -> 0
        li *= corr;
        {
            unsigned long long corr2;
            PACK2(corr2, corr, corr);
#pragma unroll
            for (int i = 0; i < 32; i++) F2MULI(o2[i], corr2);
        }

        // O += p_j * V_j (packed)
#pragma unroll
        for (int j = 0; j < BN_KV; j++) {
            float p = __expf(sv[j] - tmax);
            li += p;
            unsigned long long p2;
            PACK2(p2, p, p);
#pragma unroll
            for (int d4 = 0; d4 < 16; d4++) {
                ulonglong2 vv = *(const ulonglong2*)&Vs[s][j][d4 * 4];
                F2FMA(o2[2 * d4],     p2, vv.x);
                F2FMA(o2[2 * d4 + 1], p2, vv.y);
            }
        }
        mi = tmax;
    }

    float inv = 1.f / li;
    int b = bh >> 4;
    int h = bh & 15;
    float* op = g_attn + ((size_t)(b * SEQ + r)) * EMBED + h * HDIM;
#pragma unroll
    for (int i = 0; i < 16; i++) {
        float x0, x1, x2, x3;
        UNPACK2(x0, x1, o2[2 * i]);
        UNPACK2(x2, x3, o2[2 * i + 1]);
        float4 v;
        v.x = x0 * inv; v.y = x1 * inv; v.z = x2 * inv; v.w = x3 * inv;
        ((float4*)op)[i] = v;
    }
}

// ---------------------------------------------------------------------------
// GEMM 2: out = attn @ w_proj + b_proj. M=4096, N=1024, K=1024.
// Same packed-f32x2 double-buffered structure as qkv_gemm.
// ---------------------------------------------------------------------------
__global__ __launch_bounds__(256, 2)
void proj_gemm(const float* __restrict__ W,      // w_proj [1024,1024]
               const float* __restrict__ bias,   // [1024]
               float* __restrict__ C)            // [4096,1024]
{
    __shared__ float As[2][16][132];
    __shared__ float Bs[2][16][128];

    const int K = EMBED;
    const int NC = EMBED;
    const int tid = threadIdx.x;
    const int m0 = blockIdx.y * 128;
    const int n0 = blockIdx.x * 128;
    const int tx = tid & 15;
    const int ty = tid >> 4;

    const int arow0 = tid >> 2, ac4 = tid & 3;
    const int arow1 = arow0 + 64;
    const int brow0 = tid >> 5, bc4 = tid & 31;
    const int brow1 = brow0 + 8;

    unsigned long long acc2[8][4];
#pragma unroll
    for (int i = 0; i < 8; i++)
#pragma unroll
        for (int j = 0; j < 4; j++) acc2[i][j] = 0ULL;

    const float* A = g_attn;

    float4 ra0, ra1, rb0, rb1;
    ra0 = *(const float4*)&A[(size_t)(m0 + arow0) * K + ac4 * 4];
    ra1 = *(const float4*)&A[(size_t)(m0 + arow1) * K + ac4 * 4];
    rb0 = *(const float4*)&W[(size_t)brow0 * NC + n0 + bc4 * 4];
    rb1 = *(const float4*)&W[(size_t)brow1 * NC + n0 + bc4 * 4];

    for (int i = 0; i < K / 16; i++) {
        const int s = i & 1;

        As[s][ac4 * 4 + 0][arow0] = ra0.x;
        As[s][ac4 * 4 + 1][arow0] = ra0.y;
        As[s][ac4 * 4 + 2][arow0] = ra0.z;
        As[s][ac4 * 4 + 3][arow0] = ra0.w;
        As[s][ac4 * 4 + 0][arow1] = ra1.x;
        As[s][ac4 * 4 + 1][arow1] = ra1.y;
        As[s][ac4 * 4 + 2][arow1] = ra1.z;
        As[s][ac4 * 4 + 3][arow1] = ra1.w;
        *(float4*)&Bs[s][brow0][bc4 * 4] = rb0;
        *(float4*)&Bs[s][brow1][bc4 * 4] = rb1;

        if (i + 1 < K / 16) {
            int k0 = (i + 1) * 16;
            ra0 = *(const float4*)&A[(size_t)(m0 + arow0) * K + k0 + ac4 * 4];
            ra1 = *(const float4*)&A[(size_t)(m0 + arow1) * K + k0 + ac4 * 4];
            rb0 = *(const float4*)&W[(size_t)(k0 + brow0) * NC + n0 + bc4 * 4];
            rb1 = *(const float4*)&W[(size_t)(k0 + brow1) * NC + n0 + bc4 * 4];
        }

        __syncthreads();

#pragma unroll
        for (int kk = 0; kk < 16; kk++) {
            float a[8];
            *(float4*)&a[0] = *(const float4*)&As[s][kk][ty * 8];
            *(float4*)&a[4] = *(const float4*)&As[s][kk][ty * 8 + 4];
            ulonglong2 b01 = *(const ulonglong2*)&Bs[s][kk][tx * 8];
            ulonglong2 b23 = *(const ulonglong2*)&Bs[s][kk][tx * 8 + 4];
#pragma unroll
            for (int ii = 0; ii < 8; ii++) {
                unsigned long long a2;
                PACK2(a2, a[ii], a[ii]);
                F2FMA(acc2[ii][0], a2, b01.x);
                F2FMA(acc2[ii][1], a2, b01.y);
                F2FMA(acc2[ii][2], a2, b23.x);
                F2FMA(acc2[ii][3], a2, b23.y);
            }
        }
    }

#pragma unroll
    for (int i = 0; i < 8; i++) {
        int m = m0 + ty * 8 + i;
        int jc = n0 + tx * 8;
        float c0, c1, c2, c3, c4, c5, c6, c7;
        UNPACK2(c0, c1, acc2[i][0]);
        UNPACK2(c2, c3, acc2[i][1]);
        UNPACK2(c4, c5, acc2[i][2]);
        UNPACK2(c6, c7, acc2[i][3]);
        float4 v0, v1;
        v0.x = c0 + bias[jc + 0]; v0.y = c1 + bias[jc + 1];
        v0.z = c2 + bias[jc + 2]; v0.w = c3 + bias[jc + 3];
        v1.x = c4 + bias[jc + 4]; v1.y = c5 + bias[jc + 5];
        v1.z = c6 + bias[jc + 6]; v1.w = c7 + bias[jc + 7];
        *(float4*)&C[(size_t)m * NC + jc] = v0;
        *(float4*)&C[(size_t)m * NC + jc + 4] = v1;
    }
}

// ---------------------------------------------------------------------------
extern "C" void kernel_launch(void* const* d_in, const int* in_sizes, int n_in,
                              void* d_out, int out_size)
{
    const float* x      = (const float*)d_in[0];
    const float* w_qkv  = (const float*)d_in[1];
    const float* b_qkv  = (const float*)d_in[2];
    const float* w_proj = (const float*)d_in[3];
    const float* b_proj = (const float*)d_in[4];
    float* out = (float*)d_out;

    dim3 g1(QKV_COLS / 128, MROWS / 128);   // (24, 32)
    qkv_gemm<<<g1, 256>>>(x, w_qkv, b_qkv);

    dim3 g2(SEQ / 128, BATCH * NHEADS);     // (16, 32)
    attn_kernel<<<g2, 128>>>();

    dim3 g3(EMBED / 128, MROWS / 128);      // (8, 32)
    proj_gemm<<<g3, 256>>>(w_proj, b_proj, out);
}